// round 15
// baseline (speedup 1.0000x reference)
#include <cuda_runtime.h>
#include <cuda_bf16.h>
#include <cstdint>

#define S 2048
#define D 64
#define BH 32
#define SCALE 0.125f   // 1/sqrt(64)

#define TS   72        // bf16 row stride for smem tiles (144 B, 16B-aligned)
#define ROWB 144       // TS * 2 bytes
#define MROWB 2304     // 16 * ROWB

// ---------------------------------------------------------------------------
// mma.sync bf16 + ldmatrix helpers (sm_80 baseline PTX, compiles at compute_103)
// ---------------------------------------------------------------------------
__device__ __forceinline__ void mma_bf16(float* c, const uint32_t* a,
                                         uint32_t b0, uint32_t b1) {
    asm volatile(
        "mma.sync.aligned.m16n8k16.row.col.f32.bf16.bf16.f32 "
        "{%0,%1,%2,%3}, {%4,%5,%6,%7}, {%8,%9}, {%0,%1,%2,%3};"
        : "+f"(c[0]), "+f"(c[1]), "+f"(c[2]), "+f"(c[3])
        : "r"(a[0]), "r"(a[1]), "r"(a[2]), "r"(a[3]), "r"(b0), "r"(b1));
}

__device__ __forceinline__ uint32_t smem_u32(const void* p) {
    uint32_t a;
    asm("{ .reg .u64 t; cvta.to.shared.u64 t, %1; cvt.u32.u64 %0, t; }"
        : "=r"(a) : "l"(p));
    return a;
}

__device__ __forceinline__ void ldsm4(uint32_t* r, uint32_t a) {
    asm volatile("ldmatrix.sync.aligned.m8n8.x4.shared.b16 {%0,%1,%2,%3}, [%4];"
                 : "=r"(r[0]), "=r"(r[1]), "=r"(r[2]), "=r"(r[3]) : "r"(a));
}
__device__ __forceinline__ void ldsm4t(uint32_t* r, uint32_t a) {
    asm volatile("ldmatrix.sync.aligned.m8n8.x4.trans.shared.b16 {%0,%1,%2,%3}, [%4];"
                 : "=r"(r[0]), "=r"(r[1]), "=r"(r[2]), "=r"(r[3]) : "r"(a));
}

// split-bf16 of 2 floats
__device__ __forceinline__ void cvt2(float a, float b, uint32_t& h, uint32_t& l) {
    __nv_bfloat162 h2 = __floats2bfloat162_rn(a, b);
    float ra = a - __bfloat162float(h2.x);
    float rb = b - __bfloat162float(h2.y);
    __nv_bfloat162 l2 = __floats2bfloat162_rn(ra, rb);
    h = *reinterpret_cast<uint32_t*>(&h2);
    l = *reinterpret_cast<uint32_t*>(&l2);
}

// Load rows x 64 f32 tile (row stride ld) into hi/lo bf16 smem (stride TS).
// 128 threads; granule = 8 contiguous floats. ITERS = rows/16.
template<int ITERS>
__device__ __forceinline__ void load_tile_128t(const float* __restrict__ g,
                                               size_t ld, uint16_t* hi,
                                               uint16_t* lo, int tid) {
    #pragma unroll
    for (int j = 0; j < ITERS; j++) {
        int gidx = tid + j * 128;
        int row  = gidx >> 3;
        int i    = gidx & 7;
        const float* src = g + (size_t)row * ld + i * 8;
        float4 x = *reinterpret_cast<const float4*>(src);
        float4 y = *reinterpret_cast<const float4*>(src + 4);
        uint32_t h0, h1, h2, h3, l0, l1, l2, l3;
        cvt2(x.x, x.y, h0, l0);
        cvt2(x.z, x.w, h1, l1);
        cvt2(y.x, y.y, h2, l2);
        cvt2(y.z, y.w, h3, l3);
        int off = row * TS + i * 8;
        *reinterpret_cast<uint4*>(hi + off) = make_uint4(h0, h1, h2, h3);
        *reinterpret_cast<uint4*>(lo + off) = make_uint4(l0, l1, l2, l3);
    }
}

// ===========================================================================
// K1: scores, 64(q) x 128(k) tiles, 128 threads (4 warps), 4 ksteps.
// Writes attn = exp(score/8) for k<=q else 0 (unnormalized).
// ===========================================================================
#define K1_SMEM ((2 * 64 + 2 * 128) * TS * 2)   // 55296 B

__global__ __launch_bounds__(128) void k_scores_mma(const float* __restrict__ qg,
                                                    const float* __restrict__ kg,
                                                    float* __restrict__ attn)
{
    const int kt = blockIdx.x;     // 0..15  (k in 128-tiles)
    const int qt = blockIdx.y;     // 0..31  (q in 64-tiles)
    const int bh = blockIdx.z;
    const int q0 = qt * 64;
    const int k0 = kt * 128;
    const int tid = threadIdx.x;

    float* __restrict__ ab = attn + (size_t)bh * S * S;

    if (k0 > q0 + 63) {            // fully above diagonal: zero-fill 64x128
        const float4 z = make_float4(0.f, 0.f, 0.f, 0.f);
        #pragma unroll
        for (int i = 0; i < 16; i++) {
            int f4  = tid + i * 128;          // 2048 float4
            int row = f4 >> 5;
            int c   = (f4 & 31) * 4;
            *reinterpret_cast<float4*>(&ab[(size_t)(q0 + row) * S + k0 + c]) = z;
        }
        return;
    }

    extern __shared__ uint16_t sm[];
    uint16_t* Qhi = sm;                    // 64 x TS
    uint16_t* Qlo = sm + 64 * TS;
    uint16_t* Khi = sm + 128 * TS;         // 128 x TS
    uint16_t* Klo = sm + 256 * TS;

    load_tile_128t<4>(qg + ((size_t)bh * S + q0) * D, D, Qhi, Qlo, tid);
    load_tile_128t<8>(kg + ((size_t)bh * S + k0) * D, D, Khi, Klo, tid);
    __syncthreads();

    const int wid  = tid >> 5;
    const int lane = tid & 31;
    const int g    = lane >> 2;
    const int tg   = lane & 3;
    const int wq   = wid >> 1;     // 0..1 -> q offset 32*wq
    const int wk   = wid & 1;      // 0..1 -> k offset 64*wk
    const int mid  = lane >> 3;
    const int r7   = lane & 7;

    const uint32_t aOff = (uint32_t)(wq * 32 + (mid & 1) * 8 + r7) * ROWB
                        + (uint32_t)(mid >> 1) * 16;
    const uint32_t bOff = (uint32_t)(wk * 64 + (mid >> 1) * 8 + r7) * ROWB
                        + (uint32_t)(mid & 1) * 16;
    const uint32_t aHi = smem_u32(Qhi) + aOff, aLo = smem_u32(Qlo) + aOff;
    const uint32_t bHi = smem_u32(Khi) + bOff, bLo = smem_u32(Klo) + bOff;

    float acc[2][8][4];
    #pragma unroll
    for (int m = 0; m < 2; m++)
        #pragma unroll
        for (int n = 0; n < 8; n++)
            #pragma unroll
            for (int e = 0; e < 4; e++) acc[m][n][e] = 0.f;

    #pragma unroll
    for (int ks = 0; ks < 4; ks++) {
        const uint32_t kb = ks * 32;
        uint32_t Ah[2][4], Al[2][4];
        ldsm4(Ah[0], aHi + kb);
        ldsm4(Ah[1], aHi + MROWB + kb);
        ldsm4(Al[0], aLo + kb);
        ldsm4(Al[1], aLo + MROWB + kb);
        #pragma unroll
        for (int p = 0; p < 4; p++) {
            uint32_t Bh[4], Bl[4];
            ldsm4(Bh, bHi + p * MROWB + kb);
            ldsm4(Bl, bLo + p * MROWB + kb);
            mma_bf16(acc[0][2*p],   Ah[0], Bh[0], Bh[1]);
            mma_bf16(acc[1][2*p],   Ah[1], Bh[0], Bh[1]);
            mma_bf16(acc[0][2*p],   Ah[0], Bl[0], Bl[1]);
            mma_bf16(acc[1][2*p],   Ah[1], Bl[0], Bl[1]);
            mma_bf16(acc[0][2*p],   Al[0], Bh[0], Bh[1]);
            mma_bf16(acc[1][2*p],   Al[1], Bh[0], Bh[1]);
            mma_bf16(acc[0][2*p+1], Ah[0], Bh[2], Bh[3]);
            mma_bf16(acc[1][2*p+1], Ah[1], Bh[2], Bh[3]);
            mma_bf16(acc[0][2*p+1], Ah[0], Bl[2], Bl[3]);
            mma_bf16(acc[1][2*p+1], Ah[1], Bl[2], Bl[3]);
            mma_bf16(acc[0][2*p+1], Al[0], Bh[2], Bh[3]);
            mma_bf16(acc[1][2*p+1], Al[1], Bh[2], Bh[3]);
        }
    }

    // epilogue: exp(score*SCALE), causal mask where the tile touches diagonal
    const bool needMask = (k0 + 127 > q0);
    #pragma unroll
    for (int m = 0; m < 2; m++) {
        int gq = q0 + wq * 32 + m * 16 + g;
        #pragma unroll
        for (int n = 0; n < 8; n++) {
            int gk = k0 + wk * 64 + n * 8 + tg * 2;
            float2 v0, v1;
            v0.x = __expf(acc[m][n][0] * SCALE);
            v0.y = __expf(acc[m][n][1] * SCALE);
            v1.x = __expf(acc[m][n][2] * SCALE);
            v1.y = __expf(acc[m][n][3] * SCALE);
            if (needMask) {
                if (gk     > gq)     v0.x = 0.f;
                if (gk + 1 > gq)     v0.y = 0.f;
                if (gk     > gq + 8) v1.x = 0.f;
                if (gk + 1 > gq + 8) v1.y = 0.f;
            }
            *reinterpret_cast<float2*>(&ab[(size_t)gq * S + gk])       = v0;
            *reinterpret_cast<float2*>(&ab[(size_t)(gq + 8) * S + gk]) = v1;
        }
    }
}

// ===========================================================================
// K2: in-place row normalize: a[i] /= sum(a[0..q])  (input is exp already)
// ===========================================================================
__global__ __launch_bounds__(128) void k_softmax(float* __restrict__ attn)
{
    const int row = blockIdx.x;
    const int bh  = row >> 11;
    const int qy  = row & 2047;
    float* __restrict__ a = attn + (size_t)bh * S * S + (size_t)qy * S;
    const int len = qy + 1;

    __shared__ float buf[2048];
    __shared__ float red[4];
    const int tid  = threadIdx.x;
    const int lane = tid & 31;
    const int wrp  = tid >> 5;

    float s = 0.f;
    for (int i = tid; i < len; i += 128) {
        float v = a[i];
        buf[i] = v;
        s += v;
    }
    #pragma unroll
    for (int o = 16; o; o >>= 1) s += __shfl_xor_sync(0xffffffffu, s, o);
    if (lane == 0) red[wrp] = s;
    __syncthreads();
    s = red[0] + red[1] + red[2] + red[3];
    const float inv = 1.f / s;

    for (int i = tid; i < len; i += 128) a[i] = buf[i] * inv;
}

// ===========================================================================
// K3: out = attn @ V, 64(q) x 64(d) tiles, 128 threads, k chunks of 64.
// attn zeros above diagonal make diagonal chunks mask-free.
// ===========================================================================
#define K3_SMEM (4 * 64 * TS * 2)   // 36864 B

__global__ __launch_bounds__(128) void k_av_mma(const float* __restrict__ attn,
                                                const float* __restrict__ vg,
                                                float* __restrict__ outg)
{
    const int t  = 31 - (int)blockIdx.x;    // 64-row q tile, descending work
    const int bh = blockIdx.y;
    const int q0 = t * 64;
    const int tid = threadIdx.x;

    const float* __restrict__ ab = attn + (size_t)bh * S * S;
    const float* __restrict__ vb = vg   + (size_t)bh * S * D;
    float* __restrict__ ob       = outg + (size_t)bh * S * D;

    extern __shared__ uint16_t sm[];
    uint16_t* Phi = sm;                  // 64 x TS
    uint16_t* Plo = sm + 64 * TS;
    uint16_t* Vhi = sm + 128 * TS;       // natural [k][d], 64 x 64
    uint16_t* Vlo = sm + 192 * TS;

    const int wid  = tid >> 5;    // 0..3 -> q rows wid*16
    const int lane = tid & 31;
    const int g    = lane >> 2;
    const int tg   = lane & 3;
    const int mid  = lane >> 3;
    const int r7   = lane & 7;

    const uint32_t aOff = (uint32_t)(wid * 16 + (mid & 1) * 8 + r7) * ROWB
                        + (uint32_t)(mid >> 1) * 16;
    // V (trans): lanes address 16 k-rows; col base (mid>>1)*8 d
    const uint32_t vOff = (uint32_t)((mid & 1) * 8 + r7) * ROWB
                        + (uint32_t)((mid >> 1) * 8) * 2;
    const uint32_t pHi = smem_u32(Phi) + aOff, pLo = smem_u32(Plo) + aOff;
    const uint32_t vHi = smem_u32(Vhi) + vOff, vLo = smem_u32(Vlo) + vOff;

    float acc[8][4];
    #pragma unroll
    for (int n = 0; n < 8; n++)
        #pragma unroll
        for (int e = 0; e < 4; e++) acc[n][e] = 0.f;

    const int nch = t + 1;                 // 64-wide k chunks, k <= q0+63
    for (int ch = 0; ch < nch; ch++) {
        const int kb = ch * 64;
        load_tile_128t<4>(ab + (size_t)q0 * S + kb, S, Phi, Plo, tid);  // P 64x64
        load_tile_128t<4>(vb + (size_t)kb * D, D, Vhi, Vlo, tid);       // V 64x64
        __syncthreads();

        #pragma unroll
        for (int ks = 0; ks < 4; ks++) {
            const uint32_t akb = ks * 32;       // P: +16 bf16 cols
            const uint32_t vkb = ks * MROWB;    // V: +16 k rows
            uint32_t Ah[4], Al[4];
            ldsm4(Ah, pHi + akb);
            ldsm4(Al, pLo + akb);
            #pragma unroll
            for (int p = 0; p < 4; p++) {
                uint32_t Bh[4], Bl[4];
                ldsm4t(Bh, vHi + vkb + p * 32);
                ldsm4t(Bl, vLo + vkb + p * 32);
                mma_bf16(acc[2*p],   Ah, Bh[0], Bh[1]);
                mma_bf16(acc[2*p],   Ah, Bl[0], Bl[1]);
                mma_bf16(acc[2*p],   Al, Bh[0], Bh[1]);
                mma_bf16(acc[2*p+1], Ah, Bh[2], Bh[3]);
                mma_bf16(acc[2*p+1], Ah, Bl[2], Bl[3]);
                mma_bf16(acc[2*p+1], Al, Bh[2], Bh[3]);
            }
        }
        __syncthreads();
    }

    const int gq = q0 + wid * 16 + g;
    #pragma unroll
    for (int n = 0; n < 8; n++) {
        int gd = n * 8 + tg * 2;
        *reinterpret_cast<float2*>(&ob[(size_t)gq * D + gd]) =
            make_float2(acc[n][0], acc[n][1]);
        *reinterpret_cast<float2*>(&ob[(size_t)(gq + 8) * D + gd]) =
            make_float2(acc[n][2], acc[n][3]);
    }
}

// ===========================================================================
// launch: d_in = { q, k, v, mask } ; d_out = [ out | attn ]
// ===========================================================================
extern "C" void kernel_launch(void* const* d_in, const int* in_sizes, int n_in,
                              void* d_out, int out_size)
{
    const float* q = (const float*)d_in[0];
    const float* k = (const float*)d_in[1];
    const float* v = (const float*)d_in[2];

    float* out  = (float*)d_out;
    float* attn = out + (size_t)BH * S * D;

    static bool configured = false;
    if (!configured) {
        cudaFuncSetAttribute(k_scores_mma, cudaFuncAttributeMaxDynamicSharedMemorySize, K1_SMEM);
        cudaFuncSetAttribute(k_av_mma,     cudaFuncAttributeMaxDynamicSharedMemorySize, K3_SMEM);
        configured = true;
    }

    k_scores_mma<<<dim3(16, 32, BH), 128, K1_SMEM>>>(q, k, attn);
    k_softmax   <<<BH * S, 128>>>(attn);
    k_av_mma    <<<dim3(32, BH), 128, K3_SMEM>>>(attn, v, out);
}

// round 16
// speedup vs baseline: 1.1667x; 1.1667x over previous
#include <cuda_runtime.h>
#include <cuda_bf16.h>
#include <cstdint>

#define S 2048
#define D 64
#define BH 32
#define SCALE 0.125f   // 1/sqrt(64)

#define TS   72        // bf16 row stride for smem tiles (144 B, 16B-aligned)
#define ROWB 144       // TS * 2 bytes
#define MROWB 2304     // 16 * ROWB

// per-row sums of exp(score) (unnormalized softmax denominators)
__device__ float g_sums[BH * S];

// ---------------------------------------------------------------------------
// mma.sync bf16 + ldmatrix helpers
// ---------------------------------------------------------------------------
__device__ __forceinline__ void mma_bf16(float* c, const uint32_t* a,
                                         uint32_t b0, uint32_t b1) {
    asm volatile(
        "mma.sync.aligned.m16n8k16.row.col.f32.bf16.bf16.f32 "
        "{%0,%1,%2,%3}, {%4,%5,%6,%7}, {%8,%9}, {%0,%1,%2,%3};"
        : "+f"(c[0]), "+f"(c[1]), "+f"(c[2]), "+f"(c[3])
        : "r"(a[0]), "r"(a[1]), "r"(a[2]), "r"(a[3]), "r"(b0), "r"(b1));
}

__device__ __forceinline__ uint32_t smem_u32(const void* p) {
    uint32_t a;
    asm("{ .reg .u64 t; cvta.to.shared.u64 t, %1; cvt.u32.u64 %0, t; }"
        : "=r"(a) : "l"(p));
    return a;
}

__device__ __forceinline__ void ldsm4(uint32_t* r, uint32_t a) {
    asm volatile("ldmatrix.sync.aligned.m8n8.x4.shared.b16 {%0,%1,%2,%3}, [%4];"
                 : "=r"(r[0]), "=r"(r[1]), "=r"(r[2]), "=r"(r[3]) : "r"(a));
}
__device__ __forceinline__ void ldsm4t(uint32_t* r, uint32_t a) {
    asm volatile("ldmatrix.sync.aligned.m8n8.x4.trans.shared.b16 {%0,%1,%2,%3}, [%4];"
                 : "=r"(r[0]), "=r"(r[1]), "=r"(r[2]), "=r"(r[3]) : "r"(a));
}

// split-bf16 of 2 floats
__device__ __forceinline__ void cvt2(float a, float b, uint32_t& h, uint32_t& l) {
    __nv_bfloat162 h2 = __floats2bfloat162_rn(a, b);
    float ra = a - __bfloat162float(h2.x);
    float rb = b - __bfloat162float(h2.y);
    __nv_bfloat162 l2 = __floats2bfloat162_rn(ra, rb);
    h = *reinterpret_cast<uint32_t*>(&h2);
    l = *reinterpret_cast<uint32_t*>(&l2);
}

// Load rows x 64 f32 tile into hi/lo bf16 smem (stride TS). 256 threads.
template<int ITERS>
__device__ __forceinline__ void load_tile_64w(const float* __restrict__ g,
                                              size_t ld, uint16_t* hi,
                                              uint16_t* lo, int tid) {
    #pragma unroll
    for (int j = 0; j < ITERS; j++) {
        int gidx = tid + j * 256;
        int row  = gidx >> 3;
        int i    = gidx & 7;
        const float* src = g + (size_t)row * ld + i * 8;
        float4 x = *reinterpret_cast<const float4*>(src);
        float4 y = *reinterpret_cast<const float4*>(src + 4);
        uint32_t h0, h1, h2, h3, l0, l1, l2, l3;
        cvt2(x.x, x.y, h0, l0);
        cvt2(x.z, x.w, h1, l1);
        cvt2(y.x, y.y, h2, l2);
        cvt2(y.z, y.w, h3, l3);
        int off = row * TS + i * 8;
        *reinterpret_cast<uint4*>(hi + off) = make_uint4(h0, h1, h2, h3);
        *reinterpret_cast<uint4*>(lo + off) = make_uint4(l0, l1, l2, l3);
    }
}

// ===========================================================================
// K0: zero the sums array (BH*S floats)
// ===========================================================================
__global__ void k_zero_sums() {
    g_sums[blockIdx.x * 1024 + threadIdx.x] = 0.f;
}

// ===========================================================================
// K1: scores -> exp, 128(q) x 128(k) tiles (R12 shape), + row-sum atomics.
// attn[bh,q,k] = exp((q.k)/8) for k<=q else 0 (unnormalized).
// ===========================================================================
#define K1_SMEM (4 * 128 * TS * 2)   // 73728 B

__global__ __launch_bounds__(256) void k_scores_mma(const float* __restrict__ qg,
                                                    const float* __restrict__ kg,
                                                    float* __restrict__ attn)
{
    const int kt = blockIdx.x;
    const int qt = blockIdx.y;
    const int bh = blockIdx.z;
    const int q0 = qt * 128;
    const int k0 = kt * 128;
    const int tid = threadIdx.x;

    float* __restrict__ ab = attn + (size_t)bh * S * S;

    if (kt > qt) {                 // strictly upper: zero-fill, no sum contrib
        const float4 z = make_float4(0.f, 0.f, 0.f, 0.f);
        #pragma unroll
        for (int i = 0; i < 16; i++) {
            int f4  = tid + i * 256;
            int row = f4 >> 5;
            int c   = (f4 & 31) * 4;
            *reinterpret_cast<float4*>(&ab[(size_t)(q0 + row) * S + k0 + c]) = z;
        }
        return;
    }

    extern __shared__ uint16_t sm[];
    uint16_t* Qhi = sm;
    uint16_t* Qlo = sm + 128 * TS;
    uint16_t* Khi = sm + 2 * 128 * TS;
    uint16_t* Klo = sm + 3 * 128 * TS;

    load_tile_64w<4>(qg + ((size_t)bh * S + q0) * D, D, Qhi, Qlo, tid);
    load_tile_64w<4>(kg + ((size_t)bh * S + k0) * D, D, Khi, Klo, tid);
    __syncthreads();

    const int wid  = tid >> 5;
    const int lane = tid & 31;
    const int g    = lane >> 2;
    const int tg   = lane & 3;
    const int wq   = wid >> 1;     // q offset 32*wq
    const int wk   = wid & 1;      // k offset 64*wk
    const int mid  = lane >> 3;
    const int r7   = lane & 7;

    const uint32_t aOff = (uint32_t)(wq * 32 + (mid & 1) * 8 + r7) * ROWB
                        + (uint32_t)(mid >> 1) * 16;
    const uint32_t bOff = (uint32_t)(wk * 64 + (mid >> 1) * 8 + r7) * ROWB
                        + (uint32_t)(mid & 1) * 16;
    const uint32_t aHi = smem_u32(Qhi) + aOff, aLo = smem_u32(Qlo) + aOff;
    const uint32_t bHi = smem_u32(Khi) + bOff, bLo = smem_u32(Klo) + bOff;

    float acc[2][8][4];
    #pragma unroll
    for (int m = 0; m < 2; m++)
        #pragma unroll
        for (int n = 0; n < 8; n++)
            #pragma unroll
            for (int e = 0; e < 4; e++) acc[m][n][e] = 0.f;

    #pragma unroll
    for (int ks = 0; ks < 4; ks++) {
        const uint32_t kb = ks * 32;
        uint32_t Ah[2][4], Al[2][4];
        ldsm4(Ah[0], aHi + kb);
        ldsm4(Ah[1], aHi + MROWB + kb);
        ldsm4(Al[0], aLo + kb);
        ldsm4(Al[1], aLo + MROWB + kb);
        #pragma unroll
        for (int p = 0; p < 4; p++) {
            uint32_t Bh[4], Bl[4];
            ldsm4(Bh, bHi + p * MROWB + kb);
            ldsm4(Bl, bLo + p * MROWB + kb);
            mma_bf16(acc[0][2*p],   Ah[0], Bh[0], Bh[1]);
            mma_bf16(acc[1][2*p],   Ah[1], Bh[0], Bh[1]);
            mma_bf16(acc[0][2*p],   Ah[0], Bl[0], Bl[1]);
            mma_bf16(acc[1][2*p],   Ah[1], Bl[0], Bl[1]);
            mma_bf16(acc[0][2*p],   Al[0], Bh[0], Bh[1]);
            mma_bf16(acc[1][2*p],   Al[1], Bh[0], Bh[1]);
            mma_bf16(acc[0][2*p+1], Ah[0], Bh[2], Bh[3]);
            mma_bf16(acc[1][2*p+1], Ah[1], Bh[2], Bh[3]);
            mma_bf16(acc[0][2*p+1], Ah[0], Bl[2], Bl[3]);
            mma_bf16(acc[1][2*p+1], Ah[1], Bl[2], Bl[3]);
            mma_bf16(acc[0][2*p+1], Al[0], Bh[2], Bh[3]);
            mma_bf16(acc[1][2*p+1], Al[1], Bh[2], Bh[3]);
        }
    }

    // epilogue: exp(score*SCALE), mask on diagonal tile, accumulate row sums
    const bool diag = (kt == qt);
    float* __restrict__ sums = g_sums + bh * S;
    #pragma unroll
    for (int m = 0; m < 2; m++) {
        int gq = q0 + wq * 32 + m * 16 + g;
        float rs0 = 0.f, rs1 = 0.f;          // rows gq, gq+8
        #pragma unroll
        for (int n = 0; n < 8; n++) {
            int gk = k0 + wk * 64 + n * 8 + tg * 2;
            float2 v0, v1;
            v0.x = __expf(acc[m][n][0] * SCALE);
            v0.y = __expf(acc[m][n][1] * SCALE);
            v1.x = __expf(acc[m][n][2] * SCALE);
            v1.y = __expf(acc[m][n][3] * SCALE);
            if (diag) {
                if (gk     > gq)     v0.x = 0.f;
                if (gk + 1 > gq)     v0.y = 0.f;
                if (gk     > gq + 8) v1.x = 0.f;
                if (gk + 1 > gq + 8) v1.y = 0.f;
            }
            rs0 += v0.x + v0.y;
            rs1 += v1.x + v1.y;
            *reinterpret_cast<float2*>(&ab[(size_t)gq * S + gk])       = v0;
            *reinterpret_cast<float2*>(&ab[(size_t)(gq + 8) * S + gk]) = v1;
        }
        // reduce across the 4 lanes of this row quad (tg = 0..3)
        rs0 += __shfl_xor_sync(0xffffffffu, rs0, 1);
        rs0 += __shfl_xor_sync(0xffffffffu, rs0, 2);
        rs1 += __shfl_xor_sync(0xffffffffu, rs1, 1);
        rs1 += __shfl_xor_sync(0xffffffffu, rs1, 2);
        if (tg == 0) {
            atomicAdd(&sums[gq],     rs0);
            atomicAdd(&sums[gq + 8], rs1);
        }
    }
}

// ===========================================================================
// K3: out = attn @ V (unnormalized P), 128(q) x 64(d) tiles (R12 shape).
// While loading each P chunk, writes the NORMALIZED values back to attn.
// Output epilogue scales by invsum.
// ===========================================================================
#define K3_SMEM ((2 * 128 + 2 * 64) * TS * 2 + 128 * 4)   // + invsum = 55808 B

__global__ __launch_bounds__(256) void k_av_mma(float* __restrict__ attn,
                                                const float* __restrict__ vg,
                                                float* __restrict__ outg)
{
    const int qt = 15 - (int)blockIdx.x;    // descending work order
    const int bh = blockIdx.y;
    const int q0 = qt * 128;
    const int tid = threadIdx.x;

    float* __restrict__ ab       = attn + (size_t)bh * S * S;
    const float* __restrict__ vb = vg   + (size_t)bh * S * D;
    float* __restrict__ ob       = outg + (size_t)bh * S * D;

    extern __shared__ uint16_t sm[];
    uint16_t* Phi = sm;
    uint16_t* Plo = sm + 128 * TS;
    uint16_t* Vhi = sm + 2 * 128 * TS;   // natural [k][d], 64 x 64
    uint16_t* Vlo = Vhi + 64 * TS;
    float* inv = reinterpret_cast<float*>(Vlo + 64 * TS);   // [128]

    if (tid < 128) inv[tid] = 1.f / g_sums[bh * S + q0 + tid];
    __syncthreads();

    const int wid  = tid >> 5;
    const int lane = tid & 31;
    const int g    = lane >> 2;
    const int tg   = lane & 3;
    const int wq   = wid >> 1;    // q offset 32*wq
    const int wd   = wid & 1;     // d offset 32*wd
    const int mid  = lane >> 3;
    const int r7   = lane & 7;

    const uint32_t aOff = (uint32_t)(wq * 32 + (mid & 1) * 8 + r7) * ROWB
                        + (uint32_t)(mid >> 1) * 16;
    const uint32_t vOff = (uint32_t)((mid & 1) * 8 + r7) * ROWB
                        + (uint32_t)(wd * 32 + (mid >> 1) * 8) * 2;
    const uint32_t pHi = smem_u32(Phi) + aOff, pLo = smem_u32(Plo) + aOff;
    const uint32_t vHi = smem_u32(Vhi) + vOff, vLo = smem_u32(Vlo) + vOff;

    float acc[2][4][4];
    #pragma unroll
    for (int m = 0; m < 2; m++)
        #pragma unroll
        for (int n = 0; n < 4; n++)
            #pragma unroll
            for (int e = 0; e < 4; e++) acc[m][n][e] = 0.f;

    const int nch = (qt + 1) * 2;           // 64-wide k chunks
    for (int ch = 0; ch < nch; ch++) {
        const int kb = ch * 64;
        // P chunk 128x64: convert raw exp to bf16 for MMA; write back normalized
        #pragma unroll
        for (int j = 0; j < 4; j++) {
            int gidx = tid + j * 256;
            int row  = gidx >> 3;
            int i    = gidx & 7;
            float* src = ab + (size_t)(q0 + row) * S + kb + i * 8;
            float4 x = *reinterpret_cast<const float4*>(src);
            float4 y = *reinterpret_cast<const float4*>(src + 4);
            uint32_t h0, h1, h2, h3, l0, l1, l2, l3;
            cvt2(x.x, x.y, h0, l0);
            cvt2(x.z, x.w, h1, l1);
            cvt2(y.x, y.y, h2, l2);
            cvt2(y.z, y.w, h3, l3);
            int off = row * TS + i * 8;
            *reinterpret_cast<uint4*>(Phi + off) = make_uint4(h0, h1, h2, h3);
            *reinterpret_cast<uint4*>(Plo + off) = make_uint4(l0, l1, l2, l3);
            const float iv = inv[row];
            float4 nx = make_float4(x.x * iv, x.y * iv, x.z * iv, x.w * iv);
            float4 ny = make_float4(y.x * iv, y.y * iv, y.z * iv, y.w * iv);
            *reinterpret_cast<float4*>(src)     = nx;
            *reinterpret_cast<float4*>(src + 4) = ny;
        }
        load_tile_64w<2>(vb + (size_t)kb * D, D, Vhi, Vlo, tid);   // V 64x64
        __syncthreads();

        #pragma unroll
        for (int ks = 0; ks < 4; ks++) {
            const uint32_t akb = ks * 32;       // P: +16 bf16 cols
            const uint32_t vkb = ks * MROWB;    // V: +16 k rows
            uint32_t Ah[2][4], Al[2][4];
            ldsm4(Ah[0], pHi + akb);
            ldsm4(Ah[1], pHi + MROWB + akb);
            ldsm4(Al[0], pLo + akb);
            ldsm4(Al[1], pLo + MROWB + akb);
            #pragma unroll
            for (int p = 0; p < 2; p++) {
                uint32_t Bh[4], Bl[4];
                ldsm4t(Bh, vHi + vkb + p * 32);
                ldsm4t(Bl, vLo + vkb + p * 32);
                mma_bf16(acc[0][2*p],   Ah[0], Bh[0], Bh[1]);
                mma_bf16(acc[1][2*p],   Ah[1], Bh[0], Bh[1]);
                mma_bf16(acc[0][2*p],   Ah[0], Bl[0], Bl[1]);
                mma_bf16(acc[1][2*p],   Ah[1], Bl[0], Bl[1]);
                mma_bf16(acc[0][2*p],   Al[0], Bh[0], Bh[1]);
                mma_bf16(acc[1][2*p],   Al[1], Bh[0], Bh[1]);
                mma_bf16(acc[0][2*p+1], Ah[0], Bh[2], Bh[3]);
                mma_bf16(acc[1][2*p+1], Ah[1], Bh[2], Bh[3]);
                mma_bf16(acc[0][2*p+1], Ah[0], Bl[2], Bl[3]);
                mma_bf16(acc[1][2*p+1], Ah[1], Bl[2], Bl[3]);
                mma_bf16(acc[0][2*p+1], Al[0], Bh[2], Bh[3]);
                mma_bf16(acc[1][2*p+1], Al[1], Bh[2], Bh[3]);
            }
        }
        __syncthreads();
    }

    #pragma unroll
    for (int m = 0; m < 2; m++) {
        int lrow = wq * 32 + m * 16 + g;
        int gq = q0 + lrow;
        float iv0 = inv[lrow], iv1 = inv[lrow + 8];
        #pragma unroll
        for (int n = 0; n < 4; n++) {
            int gd = wd * 32 + n * 8 + tg * 2;
            *reinterpret_cast<float2*>(&ob[(size_t)gq * D + gd]) =
                make_float2(acc[m][n][0] * iv0, acc[m][n][1] * iv0);
            *reinterpret_cast<float2*>(&ob[(size_t)(gq + 8) * D + gd]) =
                make_float2(acc[m][n][2] * iv1, acc[m][n][3] * iv1);
        }
    }
}

// ===========================================================================
// launch: d_in = { q, k, v, mask } ; d_out = [ out | attn ]
// ===========================================================================
extern "C" void kernel_launch(void* const* d_in, const int* in_sizes, int n_in,
                              void* d_out, int out_size)
{
    const float* q = (const float*)d_in[0];
    const float* k = (const float*)d_in[1];
    const float* v = (const float*)d_in[2];

    float* out  = (float*)d_out;
    float* attn = out + (size_t)BH * S * D;

    static bool configured = false;
    if (!configured) {
        cudaFuncSetAttribute(k_scores_mma, cudaFuncAttributeMaxDynamicSharedMemorySize, K1_SMEM);
        cudaFuncSetAttribute(k_av_mma,     cudaFuncAttributeMaxDynamicSharedMemorySize, K3_SMEM);
        configured = true;
    }

    k_zero_sums <<<BH * S / 1024, 1024>>>();
    k_scores_mma<<<dim3(16, 16, BH), 256, K1_SMEM>>>(q, k, attn);
    k_av_mma    <<<dim3(16, BH), 256, K3_SMEM>>>(attn, v, out);
}

// round 17
// speedup vs baseline: 1.1722x; 1.0047x over previous
#include <cuda_runtime.h>
#include <cuda_bf16.h>
#include <cstdint>

#define S 2048
#define D 64
#define BH 32
#define SCALE 0.125f   // 1/sqrt(64)

#define TS   72        // bf16 row stride for smem tiles (144 B, 16B-aligned)
#define ROWB 144       // TS * 2 bytes
#define MROWB 2304     // 16 * ROWB

// per-row sums of exp(score) (unnormalized softmax denominators)
__device__ float g_sums[BH * S];

// ---------------------------------------------------------------------------
// mma.sync bf16 + ldmatrix helpers
// ---------------------------------------------------------------------------
__device__ __forceinline__ void mma_bf16(float* c, const uint32_t* a,
                                         uint32_t b0, uint32_t b1) {
    asm volatile(
        "mma.sync.aligned.m16n8k16.row.col.f32.bf16.bf16.f32 "
        "{%0,%1,%2,%3}, {%4,%5,%6,%7}, {%8,%9}, {%0,%1,%2,%3};"
        : "+f"(c[0]), "+f"(c[1]), "+f"(c[2]), "+f"(c[3])
        : "r"(a[0]), "r"(a[1]), "r"(a[2]), "r"(a[3]), "r"(b0), "r"(b1));
}

__device__ __forceinline__ uint32_t smem_u32(const void* p) {
    uint32_t a;
    asm("{ .reg .u64 t; cvta.to.shared.u64 t, %1; cvt.u32.u64 %0, t; }"
        : "=r"(a) : "l"(p));
    return a;
}

__device__ __forceinline__ void ldsm4(uint32_t* r, uint32_t a) {
    asm volatile("ldmatrix.sync.aligned.m8n8.x4.shared.b16 {%0,%1,%2,%3}, [%4];"
                 : "=r"(r[0]), "=r"(r[1]), "=r"(r[2]), "=r"(r[3]) : "r"(a));
}
__device__ __forceinline__ void ldsm4t(uint32_t* r, uint32_t a) {
    asm volatile("ldmatrix.sync.aligned.m8n8.x4.trans.shared.b16 {%0,%1,%2,%3}, [%4];"
                 : "=r"(r[0]), "=r"(r[1]), "=r"(r[2]), "=r"(r[3]) : "r"(a));
}

// split-bf16 of 2 floats
__device__ __forceinline__ void cvt2(float a, float b, uint32_t& h, uint32_t& l) {
    __nv_bfloat162 h2 = __floats2bfloat162_rn(a, b);
    float ra = a - __bfloat162float(h2.x);
    float rb = b - __bfloat162float(h2.y);
    __nv_bfloat162 l2 = __floats2bfloat162_rn(ra, rb);
    h = *reinterpret_cast<uint32_t*>(&h2);
    l = *reinterpret_cast<uint32_t*>(&l2);
}

// Load rows x 64 f32 tile into hi/lo bf16 smem (stride TS). 256 threads.
template<int ITERS>
__device__ __forceinline__ void load_tile_64w(const float* __restrict__ g,
                                              size_t ld, uint16_t* hi,
                                              uint16_t* lo, int tid) {
    #pragma unroll
    for (int j = 0; j < ITERS; j++) {
        int gidx = tid + j * 256;
        int row  = gidx >> 3;
        int i    = gidx & 7;
        const float* src = g + (size_t)row * ld + i * 8;
        float4 x = *reinterpret_cast<const float4*>(src);
        float4 y = *reinterpret_cast<const float4*>(src + 4);
        uint32_t h0, h1, h2, h3, l0, l1, l2, l3;
        cvt2(x.x, x.y, h0, l0);
        cvt2(x.z, x.w, h1, l1);
        cvt2(y.x, y.y, h2, l2);
        cvt2(y.z, y.w, h3, l3);
        int off = row * TS + i * 8;
        *reinterpret_cast<uint4*>(hi + off) = make_uint4(h0, h1, h2, h3);
        *reinterpret_cast<uint4*>(lo + off) = make_uint4(l0, l1, l2, l3);
    }
}

// ===========================================================================
// K0: zero the sums array (BH*S floats)
// ===========================================================================
__global__ void k_zero_sums() {
    g_sums[blockIdx.x * 1024 + threadIdx.x] = 0.f;
}

// ===========================================================================
// K1: scores -> exp, 128(q) x 128(k) tiles, + row-sum atomics.
// attn[bh,q,k] = exp((q.k)/8) for k<=q else 0 (unnormalized, streamed stores)
// ===========================================================================
#define K1_SMEM (4 * 128 * TS * 2)   // 73728 B

__global__ __launch_bounds__(256) void k_scores_mma(const float* __restrict__ qg,
                                                    const float* __restrict__ kg,
                                                    float* __restrict__ attn)
{
    const int kt = blockIdx.x;
    const int qt = blockIdx.y;
    const int bh = blockIdx.z;
    const int q0 = qt * 128;
    const int k0 = kt * 128;
    const int tid = threadIdx.x;

    float* __restrict__ ab = attn + (size_t)bh * S * S;

    if (kt > qt) {                 // strictly upper: zero-fill (streaming)
        const float4 z = make_float4(0.f, 0.f, 0.f, 0.f);
        #pragma unroll
        for (int i = 0; i < 16; i++) {
            int f4  = tid + i * 256;
            int row = f4 >> 5;
            int c   = (f4 & 31) * 4;
            __stcs(reinterpret_cast<float4*>(&ab[(size_t)(q0 + row) * S + k0 + c]), z);
        }
        return;
    }

    extern __shared__ uint16_t sm[];
    uint16_t* Qhi = sm;
    uint16_t* Qlo = sm + 128 * TS;
    uint16_t* Khi = sm + 2 * 128 * TS;
    uint16_t* Klo = sm + 3 * 128 * TS;

    load_tile_64w<4>(qg + ((size_t)bh * S + q0) * D, D, Qhi, Qlo, tid);
    load_tile_64w<4>(kg + ((size_t)bh * S + k0) * D, D, Khi, Klo, tid);
    __syncthreads();

    const int wid  = tid >> 5;
    const int lane = tid & 31;
    const int g    = lane >> 2;
    const int tg   = lane & 3;
    const int wq   = wid >> 1;     // q offset 32*wq
    const int wk   = wid & 1;      // k offset 64*wk
    const int mid  = lane >> 3;
    const int r7   = lane & 7;

    const uint32_t aOff = (uint32_t)(wq * 32 + (mid & 1) * 8 + r7) * ROWB
                        + (uint32_t)(mid >> 1) * 16;
    const uint32_t bOff = (uint32_t)(wk * 64 + (mid >> 1) * 8 + r7) * ROWB
                        + (uint32_t)(mid & 1) * 16;
    const uint32_t aHi = smem_u32(Qhi) + aOff, aLo = smem_u32(Qlo) + aOff;
    const uint32_t bHi = smem_u32(Khi) + bOff, bLo = smem_u32(Klo) + bOff;

    float acc[2][8][4];
    #pragma unroll
    for (int m = 0; m < 2; m++)
        #pragma unroll
        for (int n = 0; n < 8; n++)
            #pragma unroll
            for (int e = 0; e < 4; e++) acc[m][n][e] = 0.f;

    #pragma unroll
    for (int ks = 0; ks < 4; ks++) {
        const uint32_t kb = ks * 32;
        uint32_t Ah[2][4], Al[2][4];
        ldsm4(Ah[0], aHi + kb);
        ldsm4(Ah[1], aHi + MROWB + kb);
        ldsm4(Al[0], aLo + kb);
        ldsm4(Al[1], aLo + MROWB + kb);
        #pragma unroll
        for (int p = 0; p < 4; p++) {
            uint32_t Bh[4], Bl[4];
            ldsm4(Bh, bHi + p * MROWB + kb);
            ldsm4(Bl, bLo + p * MROWB + kb);
            mma_bf16(acc[0][2*p],   Ah[0], Bh[0], Bh[1]);
            mma_bf16(acc[1][2*p],   Ah[1], Bh[0], Bh[1]);
            mma_bf16(acc[0][2*p],   Ah[0], Bl[0], Bl[1]);
            mma_bf16(acc[1][2*p],   Ah[1], Bl[0], Bl[1]);
            mma_bf16(acc[0][2*p],   Al[0], Bh[0], Bh[1]);
            mma_bf16(acc[1][2*p],   Al[1], Bh[0], Bh[1]);
            mma_bf16(acc[0][2*p+1], Ah[0], Bh[2], Bh[3]);
            mma_bf16(acc[1][2*p+1], Ah[1], Bh[2], Bh[3]);
            mma_bf16(acc[0][2*p+1], Ah[0], Bl[2], Bl[3]);
            mma_bf16(acc[1][2*p+1], Ah[1], Bl[2], Bl[3]);
            mma_bf16(acc[0][2*p+1], Al[0], Bh[2], Bh[3]);
            mma_bf16(acc[1][2*p+1], Al[1], Bh[2], Bh[3]);
        }
    }

    // epilogue: exp(score*SCALE), mask on diagonal tile, accumulate row sums
    const bool diag = (kt == qt);
    float* __restrict__ sums = g_sums + bh * S;
    #pragma unroll
    for (int m = 0; m < 2; m++) {
        int gq = q0 + wq * 32 + m * 16 + g;
        float rs0 = 0.f, rs1 = 0.f;          // rows gq, gq+8
        #pragma unroll
        for (int n = 0; n < 8; n++) {
            int gk = k0 + wk * 64 + n * 8 + tg * 2;
            float2 v0, v1;
            v0.x = __expf(acc[m][n][0] * SCALE);
            v0.y = __expf(acc[m][n][1] * SCALE);
            v1.x = __expf(acc[m][n][2] * SCALE);
            v1.y = __expf(acc[m][n][3] * SCALE);
            if (diag) {
                if (gk     > gq)     v0.x = 0.f;
                if (gk + 1 > gq)     v0.y = 0.f;
                if (gk     > gq + 8) v1.x = 0.f;
                if (gk + 1 > gq + 8) v1.y = 0.f;
            }
            rs0 += v0.x + v0.y;
            rs1 += v1.x + v1.y;
            __stcs(reinterpret_cast<float2*>(&ab[(size_t)gq * S + gk]), v0);
            __stcs(reinterpret_cast<float2*>(&ab[(size_t)(gq + 8) * S + gk]), v1);
        }
        // reduce across the 4 lanes of this row quad (tg = 0..3)
        rs0 += __shfl_xor_sync(0xffffffffu, rs0, 1);
        rs0 += __shfl_xor_sync(0xffffffffu, rs0, 2);
        rs1 += __shfl_xor_sync(0xffffffffu, rs1, 1);
        rs1 += __shfl_xor_sync(0xffffffffu, rs1, 2);
        if (tg == 0) {
            atomicAdd(&sums[gq],     rs0);
            atomicAdd(&sums[gq + 8], rs1);
        }
    }
}

// ===========================================================================
// K3: out = attn @ V (unnormalized P), 128(q) x 64(d) tiles.
// Streams raw P in (__ldcs), writes normalized P back (__stcs), MMAs raw P,
// scales output by invsum.
// ===========================================================================
#define K3_SMEM ((2 * 128 + 2 * 64) * TS * 2 + 128 * 4)   // + invsum = 55808 B

__global__ __launch_bounds__(256) void k_av_mma(float* __restrict__ attn,
                                                const float* __restrict__ vg,
                                                float* __restrict__ outg)
{
    const int qt = 15 - (int)blockIdx.x;    // descending work order
    const int bh = blockIdx.y;
    const int q0 = qt * 128;
    const int tid = threadIdx.x;

    float* __restrict__ ab       = attn + (size_t)bh * S * S;
    const float* __restrict__ vb = vg   + (size_t)bh * S * D;
    float* __restrict__ ob       = outg + (size_t)bh * S * D;

    extern __shared__ uint16_t sm[];
    uint16_t* Phi = sm;
    uint16_t* Plo = sm + 128 * TS;
    uint16_t* Vhi = sm + 2 * 128 * TS;   // natural [k][d], 64 x 64
    uint16_t* Vlo = Vhi + 64 * TS;
    float* inv = reinterpret_cast<float*>(Vlo + 64 * TS);   // [128]

    if (tid < 128) inv[tid] = 1.f / g_sums[bh * S + q0 + tid];
    __syncthreads();

    const int wid  = tid >> 5;
    const int lane = tid & 31;
    const int g    = lane >> 2;
    const int tg   = lane & 3;
    const int wq   = wid >> 1;    // q offset 32*wq
    const int wd   = wid & 1;     // d offset 32*wd
    const int mid  = lane >> 3;
    const int r7   = lane & 7;

    const uint32_t aOff = (uint32_t)(wq * 32 + (mid & 1) * 8 + r7) * ROWB
                        + (uint32_t)(mid >> 1) * 16;
    const uint32_t vOff = (uint32_t)((mid & 1) * 8 + r7) * ROWB
                        + (uint32_t)(wd * 32 + (mid >> 1) * 8) * 2;
    const uint32_t pHi = smem_u32(Phi) + aOff, pLo = smem_u32(Plo) + aOff;
    const uint32_t vHi = smem_u32(Vhi) + vOff, vLo = smem_u32(Vlo) + vOff;

    float acc[2][4][4];
    #pragma unroll
    for (int m = 0; m < 2; m++)
        #pragma unroll
        for (int n = 0; n < 4; n++)
            #pragma unroll
            for (int e = 0; e < 4; e++) acc[m][n][e] = 0.f;

    const int nch = (qt + 1) * 2;           // 64-wide k chunks
    for (int ch = 0; ch < nch; ch++) {
        const int kb = ch * 64;
        // P chunk 128x64: stream raw exp in, stage bf16, write back normalized
        #pragma unroll
        for (int j = 0; j < 4; j++) {
            int gidx = tid + j * 256;
            int row  = gidx >> 3;
            int i    = gidx & 7;
            float* src = ab + (size_t)(q0 + row) * S + kb + i * 8;
            float4 x = __ldcs(reinterpret_cast<const float4*>(src));
            float4 y = __ldcs(reinterpret_cast<const float4*>(src + 4));
            uint32_t h0, h1, h2, h3, l0, l1, l2, l3;
            cvt2(x.x, x.y, h0, l0);
            cvt2(x.z, x.w, h1, l1);
            cvt2(y.x, y.y, h2, l2);
            cvt2(y.z, y.w, h3, l3);
            int off = row * TS + i * 8;
            *reinterpret_cast<uint4*>(Phi + off) = make_uint4(h0, h1, h2, h3);
            *reinterpret_cast<uint4*>(Plo + off) = make_uint4(l0, l1, l2, l3);
            const float iv = inv[row];
            float4 nx = make_float4(x.x * iv, x.y * iv, x.z * iv, x.w * iv);
            float4 ny = make_float4(y.x * iv, y.y * iv, y.z * iv, y.w * iv);
            __stcs(reinterpret_cast<float4*>(src),     nx);
            __stcs(reinterpret_cast<float4*>(src + 4), ny);
        }
        load_tile_64w<2>(vb + (size_t)kb * D, D, Vhi, Vlo, tid);   // V 64x64
        __syncthreads();

        #pragma unroll
        for (int ks = 0; ks < 4; ks++) {
            const uint32_t akb = ks * 32;       // P: +16 bf16 cols
            const uint32_t vkb = ks * MROWB;    // V: +16 k rows
            uint32_t Ah[2][4], Al[2][4];
            ldsm4(Ah[0], pHi + akb);
            ldsm4(Ah[1], pHi + MROWB + akb);
            ldsm4(Al[0], pLo + akb);
            ldsm4(Al[1], pLo + MROWB + akb);
            #pragma unroll
            for (int p = 0; p < 2; p++) {
                uint32_t Bh[4], Bl[4];
                ldsm4t(Bh, vHi + vkb + p * 32);
                ldsm4t(Bl, vLo + vkb + p * 32);
                mma_bf16(acc[0][2*p],   Ah[0], Bh[0], Bh[1]);
                mma_bf16(acc[1][2*p],   Ah[1], Bh[0], Bh[1]);
                mma_bf16(acc[0][2*p],   Ah[0], Bl[0], Bl[1]);
                mma_bf16(acc[1][2*p],   Ah[1], Bl[0], Bl[1]);
                mma_bf16(acc[0][2*p],   Al[0], Bh[0], Bh[1]);
                mma_bf16(acc[1][2*p],   Al[1], Bh[0], Bh[1]);
                mma_bf16(acc[0][2*p+1], Ah[0], Bh[2], Bh[3]);
                mma_bf16(acc[1][2*p+1], Ah[1], Bh[2], Bh[3]);
                mma_bf16(acc[0][2*p+1], Ah[0], Bl[2], Bl[3]);
                mma_bf16(acc[1][2*p+1], Ah[1], Bl[2], Bl[3]);
                mma_bf16(acc[0][2*p+1], Al[0], Bh[2], Bh[3]);
                mma_bf16(acc[1][2*p+1], Al[1], Bh[2], Bh[3]);
            }
        }
        __syncthreads();
    }

    #pragma unroll
    for (int m = 0; m < 2; m++) {
        int lrow = wq * 32 + m * 16 + g;
        int gq = q0 + lrow;
        float iv0 = inv[lrow], iv1 = inv[lrow + 8];
        #pragma unroll
        for (int n = 0; n < 4; n++) {
            int gd = wd * 32 + n * 8 + tg * 2;
            *reinterpret_cast<float2*>(&ob[(size_t)gq * D + gd]) =
                make_float2(acc[m][n][0] * iv0, acc[m][n][1] * iv0);
            *reinterpret_cast<float2*>(&ob[(size_t)(gq + 8) * D + gd]) =
                make_float2(acc[m][n][2] * iv1, acc[m][n][3] * iv1);
        }
    }
}

// ===========================================================================
// launch: d_in = { q, k, v, mask } ; d_out = [ out | attn ]
// ===========================================================================
extern "C" void kernel_launch(void* const* d_in, const int* in_sizes, int n_in,
                              void* d_out, int out_size)
{
    const float* q = (const float*)d_in[0];
    const float* k = (const float*)d_in[1];
    const float* v = (const float*)d_in[2];

    float* out  = (float*)d_out;
    float* attn = out + (size_t)BH * S * D;

    static bool configured = false;
    if (!configured) {
        cudaFuncSetAttribute(k_scores_mma, cudaFuncAttributeMaxDynamicSharedMemorySize, K1_SMEM);
        cudaFuncSetAttribute(k_av_mma,     cudaFuncAttributeMaxDynamicSharedMemorySize, K3_SMEM);
        configured = true;
    }

    k_zero_sums <<<BH * S / 1024, 1024>>>();
    k_scores_mma<<<dim3(16, 16, BH), 256, K1_SMEM>>>(q, k, attn);
    k_av_mma    <<<dim3(16, BH), 256, K3_SMEM>>>(attn, v, out);
}